// round 16
// baseline (speedup 1.0000x reference)
#include <cuda_runtime.h>
#include <cuda_fp16.h>
#include <math.h>
#include <stdint.h>

#define Bz 4
#define Sz 2048
#define Ez 1024
#define Hz 16
#define DKz 64

#define CNX (Bz * Sz * Ez)   // 8388608
#define CNW (Ez * Ez)        // 1048576
#define BLKX4 (CNX / 4096)   // 2048 blocks (16 elems/thread)
#define BLKW4 (CNW / 4096)   // 256

#define NSM 148
#define GEMM_GRID (4 * NSM)  // 592 persistent CTAs (QKV)
#define FLASH_GRID (2 * NSM) // 296 persistent CTAs

// ---------------------------------------------------------------------------
// Scratch (no allocs allowed)
// ---------------------------------------------------------------------------
__device__ __half g_x3[3 * CNX];    // converted Q,K,V inputs (contiguous)
__device__ __half g_w3[3 * CNW];    // converted Wq(*1/8),Wk,Wv (contiguous)
__device__ __half g_wo[CNW];        // converted Wo
__device__ __half g_qkv[3 * CNX];   // projected q(*1/8),k,v (contiguous)
__device__ __half g_ctxh[CNX];      // attention context

// ---------------------------------------------------------------------------
// Base-target PTX helpers (NO tcgen05 — harness compiles for sm_103 base)
// ---------------------------------------------------------------------------
__device__ __forceinline__ uint32_t smem_u32(const void* p) {
    uint32_t a;
    asm("{ .reg .u64 t; cvta.to.shared.u64 t, %1; cvt.u32.u64 %0, t; }"
        : "=r"(a) : "l"(p));
    return a;
}
__device__ __forceinline__ void cp16(uint32_t dst, const void* src) {
    asm volatile("cp.async.cg.shared.global [%0], [%1], 16;" :: "r"(dst), "l"(src));
}
__device__ __forceinline__ void cp_commit() {
    asm volatile("cp.async.commit_group;" ::: "memory");
}
template <int N>
__device__ __forceinline__ void cp_wait() {
    asm volatile("cp.async.wait_group %0;" :: "n"(N) : "memory");
}
__device__ __forceinline__ void ldsm4(uint32_t* r, uint32_t addr) {
    asm volatile("ldmatrix.sync.aligned.m8n8.x4.shared.b16 {%0,%1,%2,%3}, [%4];"
                 : "=r"(r[0]), "=r"(r[1]), "=r"(r[2]), "=r"(r[3]) : "r"(addr));
}
__device__ __forceinline__ void ldsm4t(uint32_t* r, uint32_t addr) {
    asm volatile("ldmatrix.sync.aligned.m8n8.x4.trans.shared.b16 {%0,%1,%2,%3}, [%4];"
                 : "=r"(r[0]), "=r"(r[1]), "=r"(r[2]), "=r"(r[3]) : "r"(addr));
}
__device__ __forceinline__ void mma_fp(float* d, const uint32_t* a,
                                       const uint32_t* b) {
    asm volatile(
        "mma.sync.aligned.m16n8k16.row.col.f32.f16.f16.f32 "
        "{%0,%1,%2,%3}, {%4,%5,%6,%7}, {%8,%9}, {%0,%1,%2,%3};"
        : "+f"(d[0]), "+f"(d[1]), "+f"(d[2]), "+f"(d[3])
        : "r"(a[0]), "r"(a[1]), "r"(a[2]), "r"(a[3]), "r"(b[0]), "r"(b[1]));
}

// ---------------------------------------------------------------------------
// Fused fp32 -> fp16 conversion, 16 elems/thread. Wq pre-scaled by 1/8.
// ---------------------------------------------------------------------------
__device__ __forceinline__ void conv16(const float* __restrict__ s,
                                       __half* __restrict__ d, int i, float sc) {
    float4 a = *(const float4*)&s[i];
    float4 b = *(const float4*)&s[i + 4];
    float4 c = *(const float4*)&s[i + 8];
    float4 e = *(const float4*)&s[i + 12];
    __half2 h[8];
    h[0] = __floats2half2_rn(a.x * sc, a.y * sc);
    h[1] = __floats2half2_rn(a.z * sc, a.w * sc);
    h[2] = __floats2half2_rn(b.x * sc, b.y * sc);
    h[3] = __floats2half2_rn(b.z * sc, b.w * sc);
    h[4] = __floats2half2_rn(c.x * sc, c.y * sc);
    h[5] = __floats2half2_rn(c.z * sc, c.w * sc);
    h[6] = __floats2half2_rn(e.x * sc, e.y * sc);
    h[7] = __floats2half2_rn(e.z * sc, e.w * sc);
    *(uint4*)&d[i] = *(uint4*)&h[0];
    *(uint4*)&d[i + 8] = *(uint4*)&h[4];
}

__global__ __launch_bounds__(256) void conv_all(
    const float* __restrict__ Q, const float* __restrict__ K,
    const float* __restrict__ V, const float* __restrict__ Wq,
    const float* __restrict__ Wk, const float* __restrict__ Wv,
    const float* __restrict__ Wo, __half* __restrict__ x3,
    __half* __restrict__ w3, __half* __restrict__ wo)
{
    const int bid = blockIdx.x;
    if (bid < 3 * BLKX4) {
        const int seg = bid / BLKX4;
        const int lb = bid - seg * BLKX4;
        const float* src = (seg == 0) ? Q : (seg == 1) ? K : V;
        __half* dst = x3 + (size_t)seg * CNX;
        conv16(src, dst, lb * 4096 + threadIdx.x * 16, 1.0f);
    } else {
        const int r = bid - 3 * BLKX4;
        const int seg = r / BLKW4;
        const int lb = r - seg * BLKW4;
        const float* src = (seg == 0) ? Wq : (seg == 1) ? Wk
                          : (seg == 2) ? Wv : Wo;
        __half* dst = (seg < 3) ? (w3 + (size_t)seg * CNW) : wo;
        conv16(src, dst, lb * 4096 + threadIdx.x * 16,
               (seg == 0) ? 0.125f : 1.0f);
    }
}

// ---------------------------------------------------------------------------
// GEMM building blocks: tile 64x128x64, 4 warps, 2-stage cp.async.
// ---------------------------------------------------------------------------
#define GBK 64
#define LDG_ 144
#define GA_B (64 * LDG_)            // 9216
#define GB_B (128 * LDG_)           // 18432
#define GSTG_B (GA_B + GB_B)        // 27648
#define GNSTG 2

// Persistent QKV GEMM, reg-capped for 4 CTAs/SM (measured-best).
__global__ __launch_bounds__(128, 4) void gemm_qkv(
    const __half* __restrict__ A0, const __half* __restrict__ W0,
    const float* __restrict__ bz0, const float* __restrict__ bz1,
    const float* __restrict__ bz2, __half* __restrict__ Ov)
{
    extern __shared__ __align__(128) char smem[];
    const int M = Bz * Sz;          // 8192
    const int N = Ez;
    const int K = Ez;
    const int tid = threadIdx.x;
    const int wid = tid >> 5;
    const int lane = tid & 31;
    const int wm = (wid >> 1) * 32;
    const int wn = (wid & 1) * 64;

    const uint32_t sb = smem_u32(smem);
    const uint32_t arow = (uint32_t)(wm + (lane & 15)) * LDG_ + (lane >> 4) * 16;
    const uint32_t bbase = (uint32_t)(wn + (lane >> 4) * 8 + (lane & 7)) * LDG_ +
                           ((lane >> 3) & 1) * 16;

    const int NIT = K / GBK;            // 16
    const int nxt = N / 128;            // 8
    const int nyt = M / 64;             // 128
    const int ntiles = 3 * nxt * nyt;

    for (int t = blockIdx.x; t < ntiles; t += gridDim.x) {
        const int x = t % nxt;
        const int rest = t / nxt;
        const int y = rest % nyt;
        const int z = rest / nyt;
        const int m0 = y * 64;
        const int n0 = x * 128;
        const __half* A  = A0 + (size_t)z * M * K;
        const __half* Bm = W0 + (size_t)z * N * K;

        float acc[2][8][4];
#pragma unroll
        for (int mt = 0; mt < 2; mt++)
#pragma unroll
            for (int nt = 0; nt < 8; nt++)
#pragma unroll
                for (int i = 0; i < 4; i++) acc[mt][nt][i] = 0.0f;

        auto load_stage = [&](int it, int slot) {
            const uint32_t stb = sb + slot * GSTG_B;
            const int k0 = it * GBK;
#pragma unroll
            for (int qq = 0; qq < 4; qq++) {
                int c = tid + qq * 128;
                int row = c >> 3, ch = c & 7;
                cp16(stb + (uint32_t)row * LDG_ + ch * 16,
                     A + (size_t)(m0 + row) * K + k0 + ch * 8);
            }
#pragma unroll
            for (int qq = 0; qq < 8; qq++) {
                int c = tid + qq * 128;
                int row = c >> 3, ch = c & 7;
                cp16(stb + GA_B + (uint32_t)row * LDG_ + ch * 16,
                     Bm + (size_t)(n0 + row) * K + k0 + ch * 8);
            }
            cp_commit();
        };

        load_stage(0, 0);

#pragma unroll 1
        for (int it = 0; it < NIT; it++) {
            const int slot = it & 1;
            cp_wait<0>();
            __syncthreads();
            if (it + 1 < NIT) load_stage(it + 1, slot ^ 1);

            const uint32_t Ab = sb + slot * GSTG_B;
            const uint32_t Bb = Ab + GA_B;
#pragma unroll
            for (int ks = 0; ks < 4; ks++) {
                uint32_t a[2][4];
#pragma unroll
                for (int mt = 0; mt < 2; mt++)
                    ldsm4(a[mt], Ab + arow + mt * (16 * LDG_) + ks * 32);
                uint32_t bf[2][4];
                ldsm4(bf[0], Bb + bbase + ks * 32);
#pragma unroll
                for (int np = 0; np < 4; np++) {
                    if (np < 3)
                        ldsm4(bf[(np + 1) & 1],
                              Bb + bbase + (np + 1) * (16 * LDG_) + ks * 32);
                    const uint32_t* b4 = bf[np & 1];
#pragma unroll
                    for (int mt = 0; mt < 2; mt++) {
                        mma_fp(acc[mt][2 * np],     a[mt], b4);
                        mma_fp(acc[mt][2 * np + 1], a[mt], b4 + 2);
                    }
                }
            }
        }

        __syncthreads();
        {
            const float* bias = (z == 0) ? bz0 : (z == 1) ? bz1 : bz2;
            const float bsc = (z == 0) ? 0.125f : 1.0f;
            const int r0 = m0 + wm + (lane >> 2);
            const int c0 = n0 + wn + 2 * (lane & 3);
            __half2* O = (__half2*)Ov + (size_t)z * M * N / 2;
#pragma unroll
            for (int mt = 0; mt < 2; mt++) {
#pragma unroll
                for (int nt = 0; nt < 8; nt++) {
                    int cc = c0 + nt * 8;
                    float bx = __ldg(&bias[cc]) * bsc;
                    float by = __ldg(&bias[cc + 1]) * bsc;
                    int ra = r0 + mt * 16;
                    O[((size_t)ra * N + cc) / 2] =
                        __floats2half2_rn(acc[mt][nt][0] + bx,
                                          acc[mt][nt][1] + by);
                    O[((size_t)(ra + 8) * N + cc) / 2] =
                        __floats2half2_rn(acc[mt][nt][2] + bx,
                                          acc[mt][nt][3] + by);
                }
            }
        }
    }
}

// Non-persistent output GEMM (measured-best): grid (8,128), fp32 out.
__global__ __launch_bounds__(128) void gemm_out(
    const __half* __restrict__ A, const __half* __restrict__ Bm,
    const float* __restrict__ bias, float* __restrict__ O, int M, int N, int K)
{
    extern __shared__ __align__(128) char smem[];
    const int tid = threadIdx.x;
    const int wid = tid >> 5;
    const int lane = tid & 31;
    const int wm = (wid >> 1) * 32;
    const int wn = (wid & 1) * 64;
    const int m0 = blockIdx.y * 64;
    const int n0 = blockIdx.x * 128;

    const uint32_t sb = smem_u32(smem);
    const uint32_t arow = (uint32_t)(wm + (lane & 15)) * LDG_ + (lane >> 4) * 16;
    const uint32_t bbase = (uint32_t)(wn + (lane >> 4) * 8 + (lane & 7)) * LDG_ +
                           ((lane >> 3) & 1) * 16;

    float acc[2][8][4];
#pragma unroll
    for (int mt = 0; mt < 2; mt++)
#pragma unroll
        for (int nt = 0; nt < 8; nt++)
#pragma unroll
            for (int i = 0; i < 4; i++) acc[mt][nt][i] = 0.0f;

    const int NIT = K / GBK;   // 16

    auto load_stage = [&](int it, int slot) {
        const uint32_t stb = sb + slot * GSTG_B;
        const int k0 = it * GBK;
#pragma unroll
        for (int qq = 0; qq < 4; qq++) {
            int c = tid + qq * 128;
            int row = c >> 3, ch = c & 7;
            cp16(stb + (uint32_t)row * LDG_ + ch * 16,
                 A + (size_t)(m0 + row) * K + k0 + ch * 8);
        }
#pragma unroll
        for (int qq = 0; qq < 8; qq++) {
            int c = tid + qq * 128;
            int row = c >> 3, ch = c & 7;
            cp16(stb + GA_B + (uint32_t)row * LDG_ + ch * 16,
                 Bm + (size_t)(n0 + row) * K + k0 + ch * 8);
        }
        cp_commit();
    };

    load_stage(0, 0);

#pragma unroll 1
    for (int it = 0; it < NIT; it++) {
        const int slot = it & 1;
        cp_wait<0>();
        __syncthreads();
        if (it + 1 < NIT) load_stage(it + 1, slot ^ 1);

        const uint32_t Ab = sb + slot * GSTG_B;
        const uint32_t Bb = Ab + GA_B;
#pragma unroll
        for (int ks = 0; ks < 4; ks++) {
            uint32_t a[2][4];
#pragma unroll
            for (int mt = 0; mt < 2; mt++)
                ldsm4(a[mt], Ab + arow + mt * (16 * LDG_) + ks * 32);
            uint32_t bf[2][4];
            ldsm4(bf[0], Bb + bbase + ks * 32);
#pragma unroll
            for (int np = 0; np < 4; np++) {
                if (np < 3)
                    ldsm4(bf[(np + 1) & 1],
                          Bb + bbase + (np + 1) * (16 * LDG_) + ks * 32);
                const uint32_t* b4 = bf[np & 1];
#pragma unroll
                for (int mt = 0; mt < 2; mt++) {
                    mma_fp(acc[mt][2 * np],     a[mt], b4);
                    mma_fp(acc[mt][2 * np + 1], a[mt], b4 + 2);
                }
            }
        }
    }

    __syncthreads();
    const int r0 = m0 + wm + (lane >> 2);
    const int c0 = n0 + wn + 2 * (lane & 3);
#pragma unroll
    for (int mt = 0; mt < 2; mt++) {
#pragma unroll
        for (int nt = 0; nt < 8; nt++) {
            int cc = c0 + nt * 8;
            float bx = __ldg(&bias[cc]);
            float by = __ldg(&bias[cc + 1]);
            int ra = r0 + mt * 16;
            *(float2*)&O[(size_t)ra * N + cc] =
                make_float2(acc[mt][nt][0] + bx, acc[mt][nt][1] + by);
            *(float2*)&O[(size_t)(ra + 8) * N + cc] =
                make_float2(acc[mt][nt][2] + bx, acc[mt][nt][3] + by);
        }
    }
}

// ---------------------------------------------------------------------------
// Persistent flash attention. Q fragments hoisted out of the KV loop
// (loop-invariant; asm ldmatrix can't be hoisted by the compiler).
// l-sum as per-lane partials, reduced once in epilogue.
// ---------------------------------------------------------------------------
#define LDH 144
#define QS_B (128 * LDH)
#define KV_B (64 * LDH)
#define KVSTG_B (2 * KV_B)

__global__ __launch_bounds__(256, 2) void flash_attn_h(
    const __half* __restrict__ Qg, const __half* __restrict__ Kg,
    const __half* __restrict__ Vg, __half* __restrict__ Og)
{
    extern __shared__ __align__(128) char smem[];
    const int tid = threadIdx.x;
    const int wid = tid >> 5;
    const int lane = tid & 31;
    const uint32_t sb = smem_u32(smem);

    const uint32_t arow = (uint32_t)(wid * 16 + (lane & 15)) * LDH +
                          (lane >> 4) * 16;
    const uint32_t bbase = (uint32_t)((lane >> 4) * 8 + (lane & 7)) * LDH +
                           ((lane >> 3) & 1) * 16;
    const uint32_t vbase = (uint32_t)(lane & 15) * LDH + (lane >> 4) * 16;
    const int NT = Sz / 64;   // 32
    const int nunits = (Sz / 128) * Hz * Bz;   // 1024

    for (int u = blockIdx.x; u < nunits; u += gridDim.x) {
        const int qt = u & 15;
        const int h  = (u >> 4) & 15;
        const int b  = u >> 8;

        const size_t hb = (size_t)b * Sz * Ez + (size_t)h * DKz;
        const __half* qg = Qg + hb + (size_t)qt * 128 * Ez;
        const __half* kg = Kg + hb;
        const __half* vg = Vg + hb;

        __syncthreads();   // all warps done with previous unit's smem

#pragma unroll
        for (int i = 0; i < 4; i++) {
            int c = tid + i * 256;
            int row = c >> 3, ch = c & 7;
            cp16(sb + row * LDH + ch * 16, qg + (size_t)row * Ez + ch * 8);
        }
        cp_commit();

        auto load_kv = [&](int kt, int s) {
            const uint32_t kb = sb + QS_B + s * KVSTG_B;
            const __half* kp = kg + (size_t)(kt * 64) * Ez;
            const __half* vp = vg + (size_t)(kt * 64) * Ez;
#pragma unroll
            for (int i = 0; i < 4; i++) {
                int c = tid + i * 256;
                int row = c >> 3, ch = c & 7;
                if (row < 64)
                    cp16(kb + row * LDH + ch * 16,
                         kp + (size_t)row * Ez + ch * 8);
                else
                    cp16(kb + KV_B + (row - 64) * LDH + ch * 16,
                         vp + (size_t)(row - 64) * Ez + ch * 8);
            }
            cp_commit();
        };

        load_kv(0, 0);
        load_kv(1, 1);

        float o[8][4];
#pragma unroll
        for (int nt = 0; nt < 8; nt++)
#pragma unroll
            for (int i = 0; i < 4; i++) o[nt][i] = 0.0f;
        float m0 = -INFINITY, m1 = -INFINITY;
        float l0 = 0.0f, l1 = 0.0f;   // per-lane partial sums
        uint32_t qa[4][4];            // hoisted Q fragments (loop-invariant)

#pragma unroll 1
        for (int it = 0; it < NT; it++) {
            const int slot = it % 3;
            if (it < NT - 1) cp_wait<1>(); else cp_wait<0>();
            __syncthreads();
            if (it + 2 < NT) load_kv(it + 2, (it + 2) % 3);

            if (it == 0) {   // Q landed with the first wait: load fragments once
#pragma unroll
                for (int ks = 0; ks < 4; ks++)
                    ldsm4(qa[ks], sb + arow + ks * 32);
            }

            const uint32_t Kb = sb + QS_B + slot * KVSTG_B;
            const uint32_t Vb = Kb + KV_B;

            float sv[8][4];
#pragma unroll
            for (int nt = 0; nt < 8; nt++)
#pragma unroll
                for (int i = 0; i < 4; i++) sv[nt][i] = 0.0f;
#pragma unroll
            for (int ks = 0; ks < 4; ks++) {
                uint32_t bf[2][4];
                ldsm4(bf[0], Kb + bbase + ks * 32);
#pragma unroll
                for (int np = 0; np < 4; np++) {
                    if (np < 3)
                        ldsm4(bf[(np + 1) & 1],
                              Kb + bbase + (np + 1) * (16 * LDH) + ks * 32);
                    const uint32_t* b4 = bf[np & 1];
                    mma_fp(sv[2 * np],     qa[ks], b4);
                    mma_fp(sv[2 * np + 1], qa[ks], b4 + 2);
                }
            }

            float mx0 = -INFINITY, mx1 = -INFINITY;
#pragma unroll
            for (int nt = 0; nt < 8; nt++) {
                mx0 = fmaxf(mx0, fmaxf(sv[nt][0], sv[nt][1]));
                mx1 = fmaxf(mx1, fmaxf(sv[nt][2], sv[nt][3]));
            }
            mx0 = fmaxf(mx0, __shfl_xor_sync(0xffffffffu, mx0, 1));
            mx0 = fmaxf(mx0, __shfl_xor_sync(0xffffffffu, mx0, 2));
            mx1 = fmaxf(mx1, __shfl_xor_sync(0xffffffffu, mx1, 1));
            mx1 = fmaxf(mx1, __shfl_xor_sync(0xffffffffu, mx1, 2));
            float mn0 = fmaxf(m0, mx0), mn1 = fmaxf(m1, mx1);
            float cr0 = __expf(m0 - mn0), cr1 = __expf(m1 - mn1);
#pragma unroll
            for (int nt = 0; nt < 8; nt++) {
                o[nt][0] *= cr0; o[nt][1] *= cr0;
                o[nt][2] *= cr1; o[nt][3] *= cr1;
            }

            float sum0 = 0.0f, sum1 = 0.0f;
#pragma unroll
            for (int ks = 0; ks < 4; ks++) {
                float e00 = __expf(sv[2 * ks][0] - mn0);
                float e01 = __expf(sv[2 * ks][1] - mn0);
                float e02 = __expf(sv[2 * ks][2] - mn1);
                float e03 = __expf(sv[2 * ks][3] - mn1);
                float e10 = __expf(sv[2 * ks + 1][0] - mn0);
                float e11 = __expf(sv[2 * ks + 1][1] - mn0);
                float e12 = __expf(sv[2 * ks + 1][2] - mn1);
                float e13 = __expf(sv[2 * ks + 1][3] - mn1);
                sum0 += e00 + e01 + e10 + e11;
                sum1 += e02 + e03 + e12 + e13;
                uint32_t pa[4];
                __half2 h0h = __floats2half2_rn(e00, e01);
                __half2 h1h = __floats2half2_rn(e02, e03);
                __half2 h2h = __floats2half2_rn(e10, e11);
                __half2 h3h = __floats2half2_rn(e12, e13);
                pa[0] = *(uint32_t*)&h0h; pa[1] = *(uint32_t*)&h1h;
                pa[2] = *(uint32_t*)&h2h; pa[3] = *(uint32_t*)&h3h;
                uint32_t vf[2][4];
                ldsm4t(vf[0], Vb + vbase + ks * (16 * LDH));
#pragma unroll
                for (int np = 0; np < 4; np++) {
                    if (np < 3)
                        ldsm4t(vf[(np + 1) & 1],
                               Vb + vbase + ks * (16 * LDH) + (np + 1) * 32);
                    const uint32_t* v4 = vf[np & 1];
                    mma_fp(o[2 * np],     pa, v4);
                    mma_fp(o[2 * np + 1], pa, v4 + 2);
                }
            }
            l0 = l0 * cr0 + sum0;
            l1 = l1 * cr1 + sum1;
            m0 = mn0; m1 = mn1;
        }

        {
            l0 += __shfl_xor_sync(0xffffffffu, l0, 1);
            l0 += __shfl_xor_sync(0xffffffffu, l0, 2);
            l1 += __shfl_xor_sync(0xffffffffu, l1, 1);
            l1 += __shfl_xor_sync(0xffffffffu, l1, 2);
            const float i0 = 1.0f / l0, i1 = 1.0f / l1;
            const int gr0 = qt * 128 + wid * 16 + (lane >> 2);
            const int cbase = h * 64 + 2 * (lane & 3);
#pragma unroll
            for (int nt = 0; nt < 8; nt++) {
                int cc = cbase + nt * 8;
                *(__half2*)&Og[((size_t)(b * Sz + gr0)) * Ez + cc] =
                    __floats2half2_rn(o[nt][0] * i0, o[nt][1] * i0);
                *(__half2*)&Og[((size_t)(b * Sz + gr0 + 8)) * Ez + cc] =
                    __floats2half2_rn(o[nt][2] * i1, o[nt][3] * i1);
            }
        }
    }
}

// ---------------------------------------------------------------------------
extern "C" void kernel_launch(void* const* d_in, const int* in_sizes, int n_in,
                              void* d_out, int out_size)
{
    const float* Q  = (const float*)d_in[0];
    const float* K  = (const float*)d_in[1];
    const float* V  = (const float*)d_in[2];
    const float* Wq = (const float*)d_in[3];
    const float* bq = (const float*)d_in[4];
    const float* Wk = (const float*)d_in[5];
    const float* bk = (const float*)d_in[6];
    const float* Wv = (const float*)d_in[7];
    const float* bv = (const float*)d_in[8];
    const float* Wo = (const float*)d_in[9];
    const float* bo = (const float*)d_in[10];
    float* out = (float*)d_out;

    __half *x3, *w3, *wo, *qkv, *ctxh;
    cudaGetSymbolAddress((void**)&x3,   g_x3);
    cudaGetSymbolAddress((void**)&w3,   g_w3);
    cudaGetSymbolAddress((void**)&wo,   g_wo);
    cudaGetSymbolAddress((void**)&qkv,  g_qkv);
    cudaGetSymbolAddress((void**)&ctxh, g_ctxh);

    cudaFuncSetAttribute(flash_attn_h,
                         cudaFuncAttributeMaxDynamicSharedMemorySize,
                         QS_B + 3 * KVSTG_B);
    cudaFuncSetAttribute(gemm_qkv,
                         cudaFuncAttributeMaxDynamicSharedMemorySize,
                         GNSTG * GSTG_B);
    cudaFuncSetAttribute(gemm_out,
                         cudaFuncAttributeMaxDynamicSharedMemorySize,
                         GNSTG * GSTG_B);

    const int M = Bz * Sz;

    conv_all<<<3 * BLKX4 + 4 * BLKW4, 256>>>(Q, K, V, Wq, Wk, Wv, Wo,
                                             x3, w3, wo);

    gemm_qkv<<<GEMM_GRID, 128, GNSTG * GSTG_B>>>(
        x3, w3, bq, bk, bv, qkv);

    flash_attn_h<<<FLASH_GRID, 256, QS_B + 3 * KVSTG_B>>>(
        qkv, qkv + (size_t)CNX, qkv + 2 * (size_t)CNX, ctxh);

    gemm_out<<<dim3(Ez / 128, M / 64), 128, GNSTG * GSTG_B>>>(
        ctxh, wo, bo, out, M, Ez, Ez);
}

// round 17
// speedup vs baseline: 1.0143x; 1.0143x over previous
#include <cuda_runtime.h>
#include <cuda_fp16.h>
#include <math.h>
#include <stdint.h>

#define Bz 4
#define Sz 2048
#define Ez 1024
#define Hz 16
#define DKz 64

#define CNX (Bz * Sz * Ez)   // 8388608
#define CNW (Ez * Ez)        // 1048576
#define BLKX4 (CNX / 4096)   // 2048 blocks (16 elems/thread)
#define BLKW4 (CNW / 4096)   // 256

#define NSM 148
#define GEMM_GRID (4 * NSM)  // 592 persistent CTAs (QKV)
#define FLASH_GRID (2 * NSM) // 296 persistent CTAs

// ---------------------------------------------------------------------------
// Scratch (no allocs allowed)
// ---------------------------------------------------------------------------
__device__ __half g_x3[3 * CNX];    // converted Q,K,V inputs (contiguous)
__device__ __half g_w3[3 * CNW];    // converted Wq(*1/8),Wk,Wv (contiguous)
__device__ __half g_wo[CNW];        // converted Wo
__device__ __half g_qkv[3 * CNX];   // projected q(*1/8),k,v (contiguous)
__device__ __half g_ctxh[CNX];      // attention context

// ---------------------------------------------------------------------------
// Base-target PTX helpers (NO tcgen05 — harness compiles for sm_103 base)
// ---------------------------------------------------------------------------
__device__ __forceinline__ uint32_t smem_u32(const void* p) {
    uint32_t a;
    asm("{ .reg .u64 t; cvta.to.shared.u64 t, %1; cvt.u32.u64 %0, t; }"
        : "=r"(a) : "l"(p));
    return a;
}
__device__ __forceinline__ void cp16(uint32_t dst, const void* src) {
    asm volatile("cp.async.cg.shared.global [%0], [%1], 16;" :: "r"(dst), "l"(src));
}
__device__ __forceinline__ void cp_commit() {
    asm volatile("cp.async.commit_group;" ::: "memory");
}
template <int N>
__device__ __forceinline__ void cp_wait() {
    asm volatile("cp.async.wait_group %0;" :: "n"(N) : "memory");
}
__device__ __forceinline__ void ldsm4(uint32_t* r, uint32_t addr) {
    asm volatile("ldmatrix.sync.aligned.m8n8.x4.shared.b16 {%0,%1,%2,%3}, [%4];"
                 : "=r"(r[0]), "=r"(r[1]), "=r"(r[2]), "=r"(r[3]) : "r"(addr));
}
__device__ __forceinline__ void ldsm4t(uint32_t* r, uint32_t addr) {
    asm volatile("ldmatrix.sync.aligned.m8n8.x4.trans.shared.b16 {%0,%1,%2,%3}, [%4];"
                 : "=r"(r[0]), "=r"(r[1]), "=r"(r[2]), "=r"(r[3]) : "r"(addr));
}
__device__ __forceinline__ void mma_fp(float* d, const uint32_t* a,
                                       const uint32_t* b) {
    asm volatile(
        "mma.sync.aligned.m16n8k16.row.col.f32.f16.f16.f32 "
        "{%0,%1,%2,%3}, {%4,%5,%6,%7}, {%8,%9}, {%0,%1,%2,%3};"
        : "+f"(d[0]), "+f"(d[1]), "+f"(d[2]), "+f"(d[3])
        : "r"(a[0]), "r"(a[1]), "r"(a[2]), "r"(a[3]), "r"(b[0]), "r"(b[1]));
}

// ---------------------------------------------------------------------------
// Fused fp32 -> fp16 conversion, 16 elems/thread. Wq pre-scaled by 1/8.
// ---------------------------------------------------------------------------
__device__ __forceinline__ void conv16(const float* __restrict__ s,
                                       __half* __restrict__ d, int i, float sc) {
    float4 a = *(const float4*)&s[i];
    float4 b = *(const float4*)&s[i + 4];
    float4 c = *(const float4*)&s[i + 8];
    float4 e = *(const float4*)&s[i + 12];
    __half2 h[8];
    h[0] = __floats2half2_rn(a.x * sc, a.y * sc);
    h[1] = __floats2half2_rn(a.z * sc, a.w * sc);
    h[2] = __floats2half2_rn(b.x * sc, b.y * sc);
    h[3] = __floats2half2_rn(b.z * sc, b.w * sc);
    h[4] = __floats2half2_rn(c.x * sc, c.y * sc);
    h[5] = __floats2half2_rn(c.z * sc, c.w * sc);
    h[6] = __floats2half2_rn(e.x * sc, e.y * sc);
    h[7] = __floats2half2_rn(e.z * sc, e.w * sc);
    *(uint4*)&d[i] = *(uint4*)&h[0];
    *(uint4*)&d[i + 8] = *(uint4*)&h[4];
}

__global__ __launch_bounds__(256) void conv_all(
    const float* __restrict__ Q, const float* __restrict__ K,
    const float* __restrict__ V, const float* __restrict__ Wq,
    const float* __restrict__ Wk, const float* __restrict__ Wv,
    const float* __restrict__ Wo, __half* __restrict__ x3,
    __half* __restrict__ w3, __half* __restrict__ wo)
{
    const int bid = blockIdx.x;
    if (bid < 3 * BLKX4) {
        const int seg = bid / BLKX4;
        const int lb = bid - seg * BLKX4;
        const float* src = (seg == 0) ? Q : (seg == 1) ? K : V;
        __half* dst = x3 + (size_t)seg * CNX;
        conv16(src, dst, lb * 4096 + threadIdx.x * 16, 1.0f);
    } else {
        const int r = bid - 3 * BLKX4;
        const int seg = r / BLKW4;
        const int lb = r - seg * BLKW4;
        const float* src = (seg == 0) ? Wq : (seg == 1) ? Wk
                          : (seg == 2) ? Wv : Wo;
        __half* dst = (seg < 3) ? (w3 + (size_t)seg * CNW) : wo;
        conv16(src, dst, lb * 4096 + threadIdx.x * 16,
               (seg == 0) ? 0.125f : 1.0f);
    }
}

// ---------------------------------------------------------------------------
// GEMM building blocks: tile 64x128x64, 4 warps, 2-stage cp.async.
// ---------------------------------------------------------------------------
#define GBK 64
#define LDG_ 144
#define GA_B (64 * LDG_)            // 9216
#define GB_B (128 * LDG_)           // 18432
#define GSTG_B (GA_B + GB_B)        // 27648
#define GNSTG 2

// Persistent QKV GEMM, reg-capped for 4 CTAs/SM (measured-best).
__global__ __launch_bounds__(128, 4) void gemm_qkv(
    const __half* __restrict__ A0, const __half* __restrict__ W0,
    const float* __restrict__ bz0, const float* __restrict__ bz1,
    const float* __restrict__ bz2, __half* __restrict__ Ov)
{
    extern __shared__ __align__(128) char smem[];
    const int M = Bz * Sz;          // 8192
    const int N = Ez;
    const int K = Ez;
    const int tid = threadIdx.x;
    const int wid = tid >> 5;
    const int lane = tid & 31;
    const int wm = (wid >> 1) * 32;
    const int wn = (wid & 1) * 64;

    const uint32_t sb = smem_u32(smem);
    const uint32_t arow = (uint32_t)(wm + (lane & 15)) * LDG_ + (lane >> 4) * 16;
    const uint32_t bbase = (uint32_t)(wn + (lane >> 4) * 8 + (lane & 7)) * LDG_ +
                           ((lane >> 3) & 1) * 16;

    const int NIT = K / GBK;            // 16
    const int nxt = N / 128;            // 8
    const int nyt = M / 64;             // 128
    const int ntiles = 3 * nxt * nyt;

    for (int t = blockIdx.x; t < ntiles; t += gridDim.x) {
        const int x = t % nxt;
        const int rest = t / nxt;
        const int y = rest % nyt;
        const int z = rest / nyt;
        const int m0 = y * 64;
        const int n0 = x * 128;
        const __half* A  = A0 + (size_t)z * M * K;
        const __half* Bm = W0 + (size_t)z * N * K;

        float acc[2][8][4];
#pragma unroll
        for (int mt = 0; mt < 2; mt++)
#pragma unroll
            for (int nt = 0; nt < 8; nt++)
#pragma unroll
                for (int i = 0; i < 4; i++) acc[mt][nt][i] = 0.0f;

        auto load_stage = [&](int it, int slot) {
            const uint32_t stb = sb + slot * GSTG_B;
            const int k0 = it * GBK;
#pragma unroll
            for (int qq = 0; qq < 4; qq++) {
                int c = tid + qq * 128;
                int row = c >> 3, ch = c & 7;
                cp16(stb + (uint32_t)row * LDG_ + ch * 16,
                     A + (size_t)(m0 + row) * K + k0 + ch * 8);
            }
#pragma unroll
            for (int qq = 0; qq < 8; qq++) {
                int c = tid + qq * 128;
                int row = c >> 3, ch = c & 7;
                cp16(stb + GA_B + (uint32_t)row * LDG_ + ch * 16,
                     Bm + (size_t)(n0 + row) * K + k0 + ch * 8);
            }
            cp_commit();
        };

        load_stage(0, 0);

#pragma unroll 1
        for (int it = 0; it < NIT; it++) {
            const int slot = it & 1;
            cp_wait<0>();
            __syncthreads();
            if (it + 1 < NIT) load_stage(it + 1, slot ^ 1);

            const uint32_t Ab = sb + slot * GSTG_B;
            const uint32_t Bb = Ab + GA_B;
#pragma unroll
            for (int ks = 0; ks < 4; ks++) {
                uint32_t a[2][4];
#pragma unroll
                for (int mt = 0; mt < 2; mt++)
                    ldsm4(a[mt], Ab + arow + mt * (16 * LDG_) + ks * 32);
                uint32_t bf[2][4];
                ldsm4(bf[0], Bb + bbase + ks * 32);
#pragma unroll
                for (int np = 0; np < 4; np++) {
                    if (np < 3)
                        ldsm4(bf[(np + 1) & 1],
                              Bb + bbase + (np + 1) * (16 * LDG_) + ks * 32);
                    const uint32_t* b4 = bf[np & 1];
#pragma unroll
                    for (int mt = 0; mt < 2; mt++) {
                        mma_fp(acc[mt][2 * np],     a[mt], b4);
                        mma_fp(acc[mt][2 * np + 1], a[mt], b4 + 2);
                    }
                }
            }
        }

        __syncthreads();
        {
            const float* bias = (z == 0) ? bz0 : (z == 1) ? bz1 : bz2;
            const float bsc = (z == 0) ? 0.125f : 1.0f;
            const int r0 = m0 + wm + (lane >> 2);
            const int c0 = n0 + wn + 2 * (lane & 3);
            __half2* O = (__half2*)Ov + (size_t)z * M * N / 2;
#pragma unroll
            for (int mt = 0; mt < 2; mt++) {
#pragma unroll
                for (int nt = 0; nt < 8; nt++) {
                    int cc = c0 + nt * 8;
                    float bx = __ldg(&bias[cc]) * bsc;
                    float by = __ldg(&bias[cc + 1]) * bsc;
                    int ra = r0 + mt * 16;
                    O[((size_t)ra * N + cc) / 2] =
                        __floats2half2_rn(acc[mt][nt][0] + bx,
                                          acc[mt][nt][1] + by);
                    O[((size_t)(ra + 8) * N + cc) / 2] =
                        __floats2half2_rn(acc[mt][nt][2] + bx,
                                          acc[mt][nt][3] + by);
                }
            }
        }
    }
}

// Non-persistent output GEMM (measured-best): grid (8,128), fp32 out.
__global__ __launch_bounds__(128) void gemm_out(
    const __half* __restrict__ A, const __half* __restrict__ Bm,
    const float* __restrict__ bias, float* __restrict__ O, int M, int N, int K)
{
    extern __shared__ __align__(128) char smem[];
    const int tid = threadIdx.x;
    const int wid = tid >> 5;
    const int lane = tid & 31;
    const int wm = (wid >> 1) * 32;
    const int wn = (wid & 1) * 64;
    const int m0 = blockIdx.y * 64;
    const int n0 = blockIdx.x * 128;

    const uint32_t sb = smem_u32(smem);
    const uint32_t arow = (uint32_t)(wm + (lane & 15)) * LDG_ + (lane >> 4) * 16;
    const uint32_t bbase = (uint32_t)(wn + (lane >> 4) * 8 + (lane & 7)) * LDG_ +
                           ((lane >> 3) & 1) * 16;

    float acc[2][8][4];
#pragma unroll
    for (int mt = 0; mt < 2; mt++)
#pragma unroll
        for (int nt = 0; nt < 8; nt++)
#pragma unroll
            for (int i = 0; i < 4; i++) acc[mt][nt][i] = 0.0f;

    const int NIT = K / GBK;   // 16

    auto load_stage = [&](int it, int slot) {
        const uint32_t stb = sb + slot * GSTG_B;
        const int k0 = it * GBK;
#pragma unroll
        for (int qq = 0; qq < 4; qq++) {
            int c = tid + qq * 128;
            int row = c >> 3, ch = c & 7;
            cp16(stb + (uint32_t)row * LDG_ + ch * 16,
                 A + (size_t)(m0 + row) * K + k0 + ch * 8);
        }
#pragma unroll
        for (int qq = 0; qq < 8; qq++) {
            int c = tid + qq * 128;
            int row = c >> 3, ch = c & 7;
            cp16(stb + GA_B + (uint32_t)row * LDG_ + ch * 16,
                 Bm + (size_t)(n0 + row) * K + k0 + ch * 8);
        }
        cp_commit();
    };

    load_stage(0, 0);

#pragma unroll 1
    for (int it = 0; it < NIT; it++) {
        const int slot = it & 1;
        cp_wait<0>();
        __syncthreads();
        if (it + 1 < NIT) load_stage(it + 1, slot ^ 1);

        const uint32_t Ab = sb + slot * GSTG_B;
        const uint32_t Bb = Ab + GA_B;
#pragma unroll
        for (int ks = 0; ks < 4; ks++) {
            uint32_t a[2][4];
#pragma unroll
            for (int mt = 0; mt < 2; mt++)
                ldsm4(a[mt], Ab + arow + mt * (16 * LDG_) + ks * 32);
            uint32_t bf[2][4];
            ldsm4(bf[0], Bb + bbase + ks * 32);
#pragma unroll
            for (int np = 0; np < 4; np++) {
                if (np < 3)
                    ldsm4(bf[(np + 1) & 1],
                          Bb + bbase + (np + 1) * (16 * LDG_) + ks * 32);
                const uint32_t* b4 = bf[np & 1];
#pragma unroll
                for (int mt = 0; mt < 2; mt++) {
                    mma_fp(acc[mt][2 * np],     a[mt], b4);
                    mma_fp(acc[mt][2 * np + 1], a[mt], b4 + 2);
                }
            }
        }
    }

    __syncthreads();
    const int r0 = m0 + wm + (lane >> 2);
    const int c0 = n0 + wn + 2 * (lane & 3);
#pragma unroll
    for (int mt = 0; mt < 2; mt++) {
#pragma unroll
        for (int nt = 0; nt < 8; nt++) {
            int cc = c0 + nt * 8;
            float bx = __ldg(&bias[cc]);
            float by = __ldg(&bias[cc + 1]);
            int ra = r0 + mt * 16;
            *(float2*)&O[(size_t)ra * N + cc] =
                make_float2(acc[mt][nt][0] + bx, acc[mt][nt][1] + by);
            *(float2*)&O[(size_t)(ra + 8) * N + cc] =
                make_float2(acc[mt][nt][2] + bx, acc[mt][nt][3] + by);
        }
    }
}

// ---------------------------------------------------------------------------
// Persistent flash attention (R15 structure; Q ldsm NOT hoisted — that
// spilled). Packed half2 max-shuffle: 2 SHFL instead of 4 per iteration.
// l-sum as per-lane partials, reduced once in epilogue.
// ---------------------------------------------------------------------------
#define LDH 144
#define QS_B (128 * LDH)
#define KV_B (64 * LDH)
#define KVSTG_B (2 * KV_B)

__global__ __launch_bounds__(256, 2) void flash_attn_h(
    const __half* __restrict__ Qg, const __half* __restrict__ Kg,
    const __half* __restrict__ Vg, __half* __restrict__ Og)
{
    extern __shared__ __align__(128) char smem[];
    const int tid = threadIdx.x;
    const int wid = tid >> 5;
    const int lane = tid & 31;
    const uint32_t sb = smem_u32(smem);

    const uint32_t arow = (uint32_t)(wid * 16 + (lane & 15)) * LDH +
                          (lane >> 4) * 16;
    const uint32_t bbase = (uint32_t)((lane >> 4) * 8 + (lane & 7)) * LDH +
                           ((lane >> 3) & 1) * 16;
    const uint32_t vbase = (uint32_t)(lane & 15) * LDH + (lane >> 4) * 16;
    const int NT = Sz / 64;   // 32
    const int nunits = (Sz / 128) * Hz * Bz;   // 1024

    for (int u = blockIdx.x; u < nunits; u += gridDim.x) {
        const int qt = u & 15;
        const int h  = (u >> 4) & 15;
        const int b  = u >> 8;

        const size_t hb = (size_t)b * Sz * Ez + (size_t)h * DKz;
        const __half* qg = Qg + hb + (size_t)qt * 128 * Ez;
        const __half* kg = Kg + hb;
        const __half* vg = Vg + hb;

        __syncthreads();   // all warps done with previous unit's smem

#pragma unroll
        for (int i = 0; i < 4; i++) {
            int c = tid + i * 256;
            int row = c >> 3, ch = c & 7;
            cp16(sb + row * LDH + ch * 16, qg + (size_t)row * Ez + ch * 8);
        }
        cp_commit();

        auto load_kv = [&](int kt, int s) {
            const uint32_t kb = sb + QS_B + s * KVSTG_B;
            const __half* kp = kg + (size_t)(kt * 64) * Ez;
            const __half* vp = vg + (size_t)(kt * 64) * Ez;
#pragma unroll
            for (int i = 0; i < 4; i++) {
                int c = tid + i * 256;
                int row = c >> 3, ch = c & 7;
                if (row < 64)
                    cp16(kb + row * LDH + ch * 16,
                         kp + (size_t)row * Ez + ch * 8);
                else
                    cp16(kb + KV_B + (row - 64) * LDH + ch * 16,
                         vp + (size_t)(row - 64) * Ez + ch * 8);
            }
            cp_commit();
        };

        load_kv(0, 0);
        load_kv(1, 1);

        float o[8][4];
#pragma unroll
        for (int nt = 0; nt < 8; nt++)
#pragma unroll
            for (int i = 0; i < 4; i++) o[nt][i] = 0.0f;
        float m0 = -INFINITY, m1 = -INFINITY;
        float l0 = 0.0f, l1 = 0.0f;   // per-lane partial sums

#pragma unroll 1
        for (int it = 0; it < NT; it++) {
            const int slot = it % 3;
            if (it < NT - 1) cp_wait<1>(); else cp_wait<0>();
            __syncthreads();
            if (it + 2 < NT) load_kv(it + 2, (it + 2) % 3);

            const uint32_t Kb = sb + QS_B + slot * KVSTG_B;
            const uint32_t Vb = Kb + KV_B;

            float sv[8][4];
#pragma unroll
            for (int nt = 0; nt < 8; nt++)
#pragma unroll
                for (int i = 0; i < 4; i++) sv[nt][i] = 0.0f;
#pragma unroll
            for (int ks = 0; ks < 4; ks++) {
                uint32_t qa[4];
                ldsm4(qa, sb + arow + ks * 32);
                uint32_t bf[2][4];
                ldsm4(bf[0], Kb + bbase + ks * 32);
#pragma unroll
                for (int np = 0; np < 4; np++) {
                    if (np < 3)
                        ldsm4(bf[(np + 1) & 1],
                              Kb + bbase + (np + 1) * (16 * LDH) + ks * 32);
                    const uint32_t* b4 = bf[np & 1];
                    mma_fp(sv[2 * np],     qa, b4);
                    mma_fp(sv[2 * np + 1], qa, b4 + 2);
                }
            }

            // row max: packed half2 reduce (2 SHFL instead of 4).
            // Online softmax is exact for any lane-consistent m-hat; fp16
            // rounding of the max only perturbs exp args by ~1e-3 abs,
            // compensated exactly by l-normalization.
            float mx0 = -INFINITY, mx1 = -INFINITY;
#pragma unroll
            for (int nt = 0; nt < 8; nt++) {
                mx0 = fmaxf(mx0, fmaxf(sv[nt][0], sv[nt][1]));
                mx1 = fmaxf(mx1, fmaxf(sv[nt][2], sv[nt][3]));
            }
            {
                __half2 mp = __floats2half2_rn(mx0, mx1);
                uint32_t mu = *(uint32_t*)&mp;
                uint32_t ot = __shfl_xor_sync(0xffffffffu, mu, 1);
                mp = __hmax2(mp, *(__half2*)&ot);
                mu = *(uint32_t*)&mp;
                ot = __shfl_xor_sync(0xffffffffu, mu, 2);
                mp = __hmax2(mp, *(__half2*)&ot);
                mx0 = __low2float(mp);
                mx1 = __high2float(mp);
            }
            float mn0 = fmaxf(m0, mx0), mn1 = fmaxf(m1, mx1);
            float cr0 = __expf(m0 - mn0), cr1 = __expf(m1 - mn1);
#pragma unroll
            for (int nt = 0; nt < 8; nt++) {
                o[nt][0] *= cr0; o[nt][1] *= cr0;
                o[nt][2] *= cr1; o[nt][3] *= cr1;
            }

            float sum0 = 0.0f, sum1 = 0.0f;
#pragma unroll
            for (int ks = 0; ks < 4; ks++) {
                float e00 = __expf(sv[2 * ks][0] - mn0);
                float e01 = __expf(sv[2 * ks][1] - mn0);
                float e02 = __expf(sv[2 * ks][2] - mn1);
                float e03 = __expf(sv[2 * ks][3] - mn1);
                float e10 = __expf(sv[2 * ks + 1][0] - mn0);
                float e11 = __expf(sv[2 * ks + 1][1] - mn0);
                float e12 = __expf(sv[2 * ks + 1][2] - mn1);
                float e13 = __expf(sv[2 * ks + 1][3] - mn1);
                sum0 += e00 + e01 + e10 + e11;
                sum1 += e02 + e03 + e12 + e13;
                uint32_t pa[4];
                __half2 h0h = __floats2half2_rn(e00, e01);
                __half2 h1h = __floats2half2_rn(e02, e03);
                __half2 h2h = __floats2half2_rn(e10, e11);
                __half2 h3h = __floats2half2_rn(e12, e13);
                pa[0] = *(uint32_t*)&h0h; pa[1] = *(uint32_t*)&h1h;
                pa[2] = *(uint32_t*)&h2h; pa[3] = *(uint32_t*)&h3h;
                uint32_t vf[2][4];
                ldsm4t(vf[0], Vb + vbase + ks * (16 * LDH));
#pragma unroll
                for (int np = 0; np < 4; np++) {
                    if (np < 3)
                        ldsm4t(vf[(np + 1) & 1],
                               Vb + vbase + ks * (16 * LDH) + (np + 1) * 32);
                    const uint32_t* v4 = vf[np & 1];
                    mma_fp(o[2 * np],     pa, v4);
                    mma_fp(o[2 * np + 1], pa, v4 + 2);
                }
            }
            l0 = l0 * cr0 + sum0;
            l1 = l1 * cr1 + sum1;
            m0 = mn0; m1 = mn1;
        }

        {
            l0 += __shfl_xor_sync(0xffffffffu, l0, 1);
            l0 += __shfl_xor_sync(0xffffffffu, l0, 2);
            l1 += __shfl_xor_sync(0xffffffffu, l1, 1);
            l1 += __shfl_xor_sync(0xffffffffu, l1, 2);
            const float i0 = 1.0f / l0, i1 = 1.0f / l1;
            const int gr0 = qt * 128 + wid * 16 + (lane >> 2);
            const int cbase = h * 64 + 2 * (lane & 3);
#pragma unroll
            for (int nt = 0; nt < 8; nt++) {
                int cc = cbase + nt * 8;
                *(__half2*)&Og[((size_t)(b * Sz + gr0)) * Ez + cc] =
                    __floats2half2_rn(o[nt][0] * i0, o[nt][1] * i0);
                *(__half2*)&Og[((size_t)(b * Sz + gr0 + 8)) * Ez + cc] =
                    __floats2half2_rn(o[nt][2] * i1, o[nt][3] * i1);
            }
        }
    }
}

// ---------------------------------------------------------------------------
extern "C" void kernel_launch(void* const* d_in, const int* in_sizes, int n_in,
                              void* d_out, int out_size)
{
    const float* Q  = (const float*)d_in[0];
    const float* K  = (const float*)d_in[1];
    const float* V  = (const float*)d_in[2];
    const float* Wq = (const float*)d_in[3];
    const float* bq = (const float*)d_in[4];
    const float* Wk = (const float*)d_in[5];
    const float* bk = (const float*)d_in[6];
    const float* Wv = (const float*)d_in[7];
    const float* bv = (const float*)d_in[8];
    const float* Wo = (const float*)d_in[9];
    const float* bo = (const float*)d_in[10];
    float* out = (float*)d_out;

    __half *x3, *w3, *wo, *qkv, *ctxh;
    cudaGetSymbolAddress((void**)&x3,   g_x3);
    cudaGetSymbolAddress((void**)&w3,   g_w3);
    cudaGetSymbolAddress((void**)&wo,   g_wo);
    cudaGetSymbolAddress((void**)&qkv,  g_qkv);
    cudaGetSymbolAddress((void**)&ctxh, g_ctxh);

    cudaFuncSetAttribute(flash_attn_h,
                         cudaFuncAttributeMaxDynamicSharedMemorySize,
                         QS_B + 3 * KVSTG_B);
    cudaFuncSetAttribute(gemm_qkv,
                         cudaFuncAttributeMaxDynamicSharedMemorySize,
                         GNSTG * GSTG_B);
    cudaFuncSetAttribute(gemm_out,
                         cudaFuncAttributeMaxDynamicSharedMemorySize,
                         GNSTG * GSTG_B);

    const int M = Bz * Sz;

    conv_all<<<3 * BLKX4 + 4 * BLKW4, 256>>>(Q, K, V, Wq, Wk, Wv, Wo,
                                             x3, w3, wo);

    gemm_qkv<<<GEMM_GRID, 128, GNSTG * GSTG_B>>>(
        x3, w3, bq, bk, bv, qkv);

    flash_attn_h<<<FLASH_GRID, 256, QS_B + 3 * KVSTG_B>>>(
        qkv, qkv + (size_t)CNX, qkv + 2 * (size_t)CNX, ctxh);

    gemm_out<<<dim3(Ez / 128, M / 64), 128, GNSTG * GSTG_B>>>(
        ctxh, wo, bo, out, M, Ez, Ez);
}